// round 16
// baseline (speedup 1.0000x reference)
#include <cuda_runtime.h>
#include <math.h>
#include <stdint.h>

// Problem constants (fixed shapes from reference)
#define BB 32
#define PP 8732
#define CC 81
#define KK 16
#define THRESH 0.5f
#define SPLIT_A 35               // 35*256 = 8960 >= 8732: one prior per thread
#define CE_ROWS 64
#define NROWS (BB * PP)          // 279424 = 64 * 4366
#define CE_BLOCKS (NROWS / CE_ROWS)
#define NBINS 1024               // linear bins, width 1/64, clamp at bin 1023

// Scratch (no allocations allowed). Statically zero-initialized; every run
// leaves all of this back at zero (consumers reset what they read).
__device__ float g_ce_neg[BB * PP];
__device__ unsigned char g_kb[BB * PP];          // kbest (bits 0-3) | pos flag (bit 4)
__device__ unsigned long long g_key[BB * KK];    // packed per-object argmax keys
__device__ int    g_hist[BB * NBINS];            // per-batch linear-bin counts
__device__ float  g_fsum[BB * NBINS];            // per-batch linear-bin value sums
__device__ int    g_cdone[BB];                   // per-batch ce-block done counters
__device__ int    g_npos[BB];
__device__ int    g_npos_total;
__device__ double g_box;
__device__ double g_pos_ce;
__device__ double g_hard;
__device__ unsigned int g_done;

// ---------------------------------------------------------------------------
// Correctly-rounded fp32 division, fast path only (Markstein sequence).
// Bit-exact vs '/' for normal operands with normal intermediates — our
// domain: a in [0, 0.25], b in [~1e-3, 1.2]. a == 0 yields exactly 0.
// ---------------------------------------------------------------------------
__device__ __forceinline__ float exact_div(float a, float b) {
    float y;
    asm("rcp.approx.f32 %0, %1;" : "=f"(y) : "f"(b));
    float e  = __fmaf_rn(-b, y, 1.0f);
    float y1 = __fmaf_rn(e, y, y);
    float q  = __fmul_rn(a, y1);
    float r  = __fmaf_rn(-b, q, a);
    return __fmaf_rn(r, y1, q);
}

// ---------------------------------------------------------------------------
// Kernel 1: IoU + argmaxes (unchanged champion). Grid (BB, SPLIT_A) x 256.
// ---------------------------------------------------------------------------
__global__ __launch_bounds__(256) void iou_kernel(
    const float* __restrict__ boxes,    // [B,K,4] xyxy
    const float* __restrict__ priors)   // [P,4] cxcywh
{
    __shared__ float4 sbox[KK];
    __shared__ float  sarea[KK];
    __shared__ unsigned long long skey[KK][8];

    const int b    = blockIdx.x;
    const int tid  = threadIdx.x;
    const int lane = tid & 31;
    const int warp = tid >> 5;

    if (tid < KK) {
        float4 bx = reinterpret_cast<const float4*>(boxes)[b * KK + tid];
        sbox[tid]  = bx;
        sarea[tid] = (bx.z - bx.x) * (bx.w - bx.y);
    }
    __syncthreads();

    const int p = blockIdx.y * 256 + tid;
    const bool valid = (p < PP);

    unsigned int ib[KK];
    if (valid) {
        float4 pc = reinterpret_cast<const float4*>(priors)[p];
        float px0 = pc.x - pc.z * 0.5f;
        float py0 = pc.y - pc.w * 0.5f;
        float px1 = pc.x + pc.z * 0.5f;
        float py1 = pc.y + pc.w * 0.5f;
        float parea = (px1 - px0) * (py1 - py0);

        float vbest = -1e30f;
        int   kbest = 0;
#pragma unroll
        for (int k = 0; k < KK; k++) {
            float4 bx = sbox[k];
            float ltx = fmaxf(bx.x, px0);
            float lty = fmaxf(bx.y, py0);
            float rbx = fminf(bx.z, px1);
            float rby = fminf(bx.w, py1);
            float w = fmaxf(rbx - ltx, 0.0f);
            float h = fmaxf(rby - lty, 0.0f);
            float inter = w * h;
            float iou = exact_div(inter, sarea[k] + parea - inter); // == rn(a/b)
            ib[k] = __float_as_uint(iou);                     // iou >= 0
            if (iou > vbest) { vbest = iou; kbest = k; }      // first max over k
        }
        g_kb[b * PP + p] = (unsigned char)(kbest | ((vbest < THRESH) ? 0 : 16));
    } else {
#pragma unroll
        for (int k = 0; k < KK; k++) ib[k] = 0u;
    }

    const int pbase = blockIdx.y * 256 + warp * 32;   // p at lane 0 of this warp
#pragma unroll
    for (int k = 0; k < KK; k++) {
        unsigned int m = __reduce_max_sync(0xffffffffu, ib[k]);
        unsigned int ball = __ballot_sync(0xffffffffu, ib[k] == m);
        int src = __ffs(ball) - 1;                    // lowest lane = lowest p
        if (lane == 0)
            skey[k][warp] = ((unsigned long long)m << 32) |
                            (unsigned int)(~(unsigned int)(pbase + src));
    }
    __syncthreads();
    if (tid < KK) {
        unsigned long long best = skey[tid][0];
#pragma unroll
        for (int w = 1; w < 8; w++) {
            unsigned long long o = skey[tid][w];
            if (o > best) best = o;
        }
        atomicMax(&g_key[b * KK + tid], best);
    }
}

// ---------------------------------------------------------------------------
// In-kernel per-batch selection: exact top-M sum of ce_neg for batch b,
// run by the LAST ce block to finish that batch, with 256 threads.
// 1024-bin suffix select (4 bins/thread, registers) -> threshold bin;
// above-bin sums from g_fsum; compact threshold-bin members into sbuf;
// exact 4x8-bit radix over the compact list; ties contribute rem*T.
// Also resets all per-batch scratch for the next graph replay, and the
// 32nd select finalizes the scalar loss.
// ---------------------------------------------------------------------------
__device__ __noinline__ void select_batch(int b, float* sbuf, float* out)
{
    __shared__ int    swtot[8];
    __shared__ int    shsum[8];
    __shared__ double sdacc[8];
    __shared__ int    s_bin, s_rem, s_n, s_M;

    const int tid  = threadIdx.x;
    const int lane = tid & 31;
    const int warp = tid >> 5;
    const float* __restrict__ src = g_ce_neg + b * PP;

    int*   rhist = (int*)sbuf;          // 256 ints for radix passes
    float* cl    = sbuf + 256;          // compact list
    const int CAP = CE_ROWS * CC - 256; // 4928

    __threadfence();                    // acquire side of the done-counter

    // load + reset the 1024-bin histogram and per-bin float sums
    int   c[4];
    float f[4];
#pragma unroll
    for (int j = 0; j < 4; j++) {
        int bin = tid * 4 + j;
        c[j] = g_hist[b * NBINS + bin];  g_hist[b * NBINS + bin] = 0;
        f[j] = g_fsum[b * NBINS + bin];  g_fsum[b * NBINS + bin] = 0.0f;
    }
    if (tid == 0) {
        int M = 3 * g_npos[b];
        if (M > PP) M = PP;
        s_M = M;
        s_n = 0;
        g_npos[b]  = 0;                 // reset for next replay
        g_cdone[b] = 0;                 // reset for next replay
    }
    if (tid < KK) g_key[b * KK + tid] = 0ull;   // reset for next replay
    __syncthreads();
    const int M = s_M;

    if (M > 0) {
        // descending-cumulative suffix over 1024 bins (4 bins/thread)
        int s3 = c[3], s2 = c[2] + s3, s1 = c[1] + s2, s0 = c[0] + s1;
        int tot = s0;
        int sfx = tot;
#pragma unroll
        for (int off = 1; off < 32; off <<= 1) {
            int o = __shfl_down_sync(0xffffffffu, sfx, off);
            if (lane + off < 32) sfx += o;
        }
        if (lane == 0) swtot[warp] = sfx;
        __syncthreads();
        if (tid < 8) {
            int v = 0;
            for (int w2 = tid + 1; w2 < 8; w2++) v += swtot[w2];
            shsum[tid] = v;
        }
        __syncthreads();
        const int base = shsum[warp] + (sfx - tot);
        {
            int S0 = base + s0, S1 = base + s1, S2 = base + s2, S3 = base + s3;
            if (S0 >= M && S0 - c[0] < M) { s_bin = tid * 4 + 0; s_rem = M - (S0 - c[0]); }
            if (S1 >= M && S1 - c[1] < M) { s_bin = tid * 4 + 1; s_rem = M - (S1 - c[1]); }
            if (S2 >= M && S2 - c[2] < M) { s_bin = tid * 4 + 2; s_rem = M - (S2 - c[2]); }
            if (S3 >= M && S3 - c[3] < M) { s_bin = tid * 4 + 3; s_rem = M - (S3 - c[3]); }
        }
        __syncthreads();
        const int cbin = s_bin;
        int rem = s_rem;
        __syncthreads();

        // above-threshold-bin exact sums (from per-bin fsum)
        double acc = 0.0;
#pragma unroll
        for (int j = 0; j < 4; j++)
            if (tid * 4 + j > cbin) acc += (double)f[j];

        // one sweep: compact threshold-bin members
        for (int i = tid; i < PP; i += 256) {
            float vv = src[i];
            int bin = min((int)(vv * 64.0f), NBINS - 1);
            if (bin == cbin) {
                int ix = atomicAdd(&s_n, 1);
                if (ix < CAP) cl[ix] = vv;
            }
        }
        __syncthreads();
        int n = s_n;
        if (n > CAP) n = CAP;

        // exact radix over the compact list: 4 passes of 8 bits
        unsigned int pfx = 0;
#pragma unroll
        for (int pass = 0; pass < 4; pass++) {
            rhist[tid] = 0;
            __syncthreads();
            for (int i = tid; i < n; i += 256) {
                unsigned int u = __float_as_uint(cl[i]);
                bool ok; unsigned int bn;
                if (pass == 0)      { ok = true;                 bn = u >> 24; }
                else if (pass == 1) { ok = ((u >> 24) == pfx);   bn = (u >> 16) & 255u; }
                else if (pass == 2) { ok = ((u >> 16) == pfx);   bn = (u >> 8)  & 255u; }
                else                { ok = ((u >> 8)  == pfx);   bn = u & 255u; }
                if (ok) atomicAdd(&rhist[bn], 1);
            }
            __syncthreads();
            int cc = rhist[tid];
            int sx2 = cc;
#pragma unroll
            for (int off = 1; off < 32; off <<= 1) {
                int o = __shfl_down_sync(0xffffffffu, sx2, off);
                if (lane + off < 32) sx2 += o;
            }
            if (lane == 0) swtot[warp] = sx2;
            __syncthreads();
            if (tid < 8) {
                int v = 0;
                for (int w2 = tid + 1; w2 < 8; w2++) v += swtot[w2];
                shsum[tid] = v;
            }
            __syncthreads();
            int SS = shsum[warp] + sx2;
            if (SS >= rem && SS - cc < rem) { s_bin = tid; s_rem = rem - (SS - cc); }
            __syncthreads();
            pfx = (pfx << 8) | (unsigned int)s_bin;
            rem = s_rem;
            __syncthreads();
        }

        const unsigned int Tu = pfx;
        const float T = __uint_as_float(Tu);

        for (int i = tid; i < n; i += 256) {
            float vv = cl[i];
            if (__float_as_uint(vv) > Tu) acc += (double)vv;
        }
#pragma unroll
        for (int off = 16; off > 0; off >>= 1)
            acc += __shfl_xor_sync(0xffffffffu, acc, off);
        if (lane == 0) sdacc[warp] = acc;
        __syncthreads();
        if (tid == 0) {
            double t = 0.0;
#pragma unroll
            for (int w2 = 0; w2 < 8; w2++) t += sdacc[w2];
            atomicAdd(&g_hard, t + (double)rem * (double)T);
        }
        __syncthreads();
    }

    // last of the 32 batch-selects finalizes the loss and resets scalars
    if (tid == 0) {
        __threadfence();
        unsigned int old = atomicAdd(&g_done, 1u);
        if (old == BB - 1) {
            double np = (double)g_npos_total;
            out[0] = (float)((g_pos_ce + g_hard) / np + g_box / (np * 4.0));
            g_pos_ce = 0.0;
            g_hard   = 0.0;
            g_box    = 0.0;
            g_npos_total = 0;
            g_done   = 0u;
        }
    }
}

// ---------------------------------------------------------------------------
// Kernel 2: fused assign + CE + histogram build + (per-batch last block)
// selection + finalize. One block per 64 rows, 256 threads.
// ---------------------------------------------------------------------------
__global__ __launch_bounds__(256, 6) void ce_kernel(
    const float* __restrict__ locs,     // [B,P,4]
    const float* __restrict__ scores,   // [B*P, C]
    const float* __restrict__ boxes,    // [B,K,4] xyxy
    const int*   __restrict__ labels,   // [B,K]
    const float* __restrict__ priors,   // [P,4] cxcywh
    float* __restrict__ out)
{
    __shared__ float sx[CE_ROWS * CC];   // 20736 B (reused by select)
    __shared__ float sp[256];            // exp partials
    __shared__ float sbx[2][KK * 4];
    __shared__ int   slab[2][KK];
    __shared__ int   spfo[2][KK];
    __shared__ int    snpos[2];
    __shared__ double sposce[2];
    __shared__ double sbox[2];
    __shared__ int    s_do[2];

    const int tid  = threadIdx.x;
    const size_t row0 = (size_t)blockIdx.x * CE_ROWS;
    const int b0 = (int)(row0 / PP);
    const int b1 = (int)((row0 + CE_ROWS - 1) / PP);

    if (tid < 2) { snpos[tid] = 0; sposce[tid] = 0.0; sbox[tid] = 0.0; }
#pragma unroll
    for (int j = 0; j < 2; j++) {
        int bb = b0 + j;
        if (bb <= b1) {
            if (tid < KK * 4) sbx[j][tid] = boxes[bb * KK * 4 + tid];
            if (tid < KK) {
                slab[j][tid] = labels[bb * KK + tid];
                spfo[j][tid] = (int)(~(unsigned int)(g_key[bb * KK + tid] & 0xffffffffu));
            }
        }
    }

    // Stage: 64*81 = 5184 floats = 1296 float4 (row0*81*4 bytes 16B-aligned)
    const float4* src = reinterpret_cast<const float4*>(scores + row0 * CC);
    float4* dst = reinterpret_cast<float4*>(sx);
#pragma unroll
    for (int i = 0; i < 6; i++) {        // 6*256 = 1536 >= 1296
        int idx = tid + i * 256;
        if (idx < (CE_ROWS * CC) / 4) dst[idx] = src[idx];
    }
    __syncthreads();

    // exp phase: 4 threads per row; quarter q covers cols [q*20, q*20+20)
    // (+ col 80 for q==3). Row stride 81 odd -> conflict-free.
    {
        const int r = tid & 63;
        const int q = tid >> 6;
        const float* s = sx + r * CC;
        const int c0 = q * 20;
        float a0 = 0.f, a1 = 0.f, a2 = 0.f, a3 = 0.f;
#pragma unroll
        for (int i = 0; i < 5; i++) {
            int c = c0 + i * 4;
            a0 += __expf(s[c + 0]);
            a1 += __expf(s[c + 1]);
            a2 += __expf(s[c + 2]);
            a3 += __expf(s[c + 3]);
        }
        if (q == 3) a0 += __expf(s[80]);
        sp[tid] = (a0 + a1) + (a2 + a3);
    }
    __syncthreads();

    if (tid < CE_ROWS) {
        const int row = (int)row0 + tid;
        int b = b0, p = row - b0 * PP;
        if (p >= PP) { b++; p -= PP; }
        const int j = b - b0;

        // force-assign label
        unsigned char kb = g_kb[row];
        int k   = kb & 15;
        int pos = (kb >> 4) & 1;
#pragma unroll
        for (int kk = 0; kk < KK; kk++)
            if (p == spfo[j][kk]) { k = kk; pos = 1; }   // ascending k, last wins
        const int lbl = pos ? slab[j][k] : 0;

        float lse = __logf((sp[tid] + sp[tid + 64]) +
                           (sp[tid + 128] + sp[tid + 192]));
        float ce = lse - sx[tid * CC + lbl];

        float v;
        if (lbl != 0) {
            v = 0.0f;
            g_ce_neg[row] = 0.0f;
            // encode + L1 for this positive prior
            float4 pc = reinterpret_cast<const float4*>(priors)[p];
            float bx0 = sbx[j][k * 4 + 0], by0 = sbx[j][k * 4 + 1];
            float bx1 = sbx[j][k * 4 + 2], by1 = sbx[j][k * 4 + 3];
            float t0 = ((bx0 + bx1) * 0.5f - pc.x) / (pc.z / 10.0f);
            float t1 = ((by0 + by1) * 0.5f - pc.y) / (pc.w / 10.0f);
            float t2 = logf((bx1 - bx0) / pc.z) * 5.0f;
            float t3 = logf((by1 - by0) / pc.w) * 5.0f;
            float4 pl = reinterpret_cast<const float4*>(locs)[row];
            float l1 = fabsf(pl.x - t0) + fabsf(pl.y - t1) +
                       fabsf(pl.z - t2) + fabsf(pl.w - t3);
            atomicAdd(&sposce[j], (double)ce);
            atomicAdd(&sbox[j],   (double)l1);
            atomicAdd(&snpos[j],  1);
        } else {
            v = fmaxf(ce, 0.0f);        // clamp: keeps uint order exact in select
            g_ce_neg[row] = v;
        }

        // selection histogram (positives contribute v=0 -> bin 0, count only)
        int bin = (lbl != 0) ? 0 : min((int)(v * 64.0f), NBINS - 1);
        atomicAdd(&g_hist[b * NBINS + bin], 1);
        if (v > 0.0f) atomicAdd(&g_fsum[b * NBINS + bin], v);
    }

    __syncthreads();
    if (tid < 2) {
        int bb = b0 + tid;
        if (bb <= b1 && snpos[tid] > 0) {
            atomicAdd(&g_npos[bb], snpos[tid]);
            atomicAdd(&g_npos_total, snpos[tid]);
            atomicAdd(&g_pos_ce, sposce[tid]);
            atomicAdd(&g_box,    sbox[tid]);
        }
    }
    __syncthreads();

    // per-batch done counters; the completing block runs that batch's select
    if (tid == 0) {
        s_do[0] = 0;
        s_do[1] = 0;
        __threadfence();
        const int nb = (b1 > b0) ? 2 : 1;
        for (int j = 0; j < nb; j++) {
            const int bb = b0 + j;
            const long long lo = (long long)bb * PP;
            const int target = (int)(((lo + PP - 1) >> 6) - (lo >> 6) + 1);
            int old = atomicAdd(&g_cdone[bb], 1);
            if (old == target - 1) s_do[j] = 1;
        }
    }
    __syncthreads();
    if (s_do[0]) select_batch(b0, sx, out);
    if (s_do[1]) select_batch(b0 + 1, sx, out);
}

extern "C" void kernel_launch(void* const* d_in, const int* in_sizes, int n_in,
                              void* d_out, int out_size)
{
    const float* locs   = (const float*)d_in[0];  // [B,P,4]
    const float* scores = (const float*)d_in[1];  // [B,P,C]
    const float* boxes  = (const float*)d_in[2];  // [B,K,4]
    const int*   labels = (const int*)d_in[3];    // [B,K]
    const float* priors = (const float*)d_in[4];  // [P,4]
    float* out = (float*)d_out;

    iou_kernel<<<dim3(BB, SPLIT_A), 256>>>(boxes, priors);
    ce_kernel<<<CE_BLOCKS, 256>>>(locs, scores, boxes, labels, priors, out);
}

// round 17
// speedup vs baseline: 1.1308x; 1.1308x over previous
#include <cuda_runtime.h>
#include <math.h>
#include <stdint.h>

// Problem constants (fixed shapes from reference)
#define BB 32
#define PP 8732
#define CC 81
#define KK 16
#define THRESH 0.5f
#define SPLIT_A 35               // 35*256 = 8960 >= 8732: one prior per thread
#define CE_ROWS 64
#define NROWS (BB * PP)          // 279424 = 64 * 4366
#define CE_BLOCKS (NROWS / CE_ROWS)
#define NBINS 2048

// Scratch (no allocations allowed). Statically zero-initialized; every run
// leaves all of this back at zero (consumers reset what they read).
__device__ float g_ce_neg[BB * PP];
__device__ unsigned char g_kb[BB * PP];          // kbest (bits 0-3) | pos flag (bit 4)
__device__ unsigned long long g_key[BB * KK];    // packed per-object argmax keys
__device__ int    g_hist[BB * NBINS];            // per-batch linear-bin counts
__device__ float  g_fsum[BB * NBINS];            // per-batch linear-bin value sums
__device__ int    g_npos[BB];
__device__ int    g_npos_total;
__device__ double g_box;
__device__ double g_pos_ce;
__device__ double g_hard;
__device__ unsigned int g_done;

// ---------------------------------------------------------------------------
// Correctly-rounded fp32 division, fast path only (Markstein sequence).
// Bit-exact vs '/' for normal operands with normal intermediates — our
// domain: a in [0, 0.25], b in [~1e-3, 1.2]. a == 0 yields exactly 0.
// ---------------------------------------------------------------------------
__device__ __forceinline__ float exact_div(float a, float b) {
    float y;
    asm("rcp.approx.f32 %0, %1;" : "=f"(y) : "f"(b));
    float e  = __fmaf_rn(-b, y, 1.0f);
    float y1 = __fmaf_rn(e, y, y);
    float q  = __fmul_rn(a, y1);
    float r  = __fmaf_rn(-b, q, a);
    return __fmaf_rn(r, y1, q);
}

// ---------------------------------------------------------------------------
// Kernel 1: IoU + argmaxes. Triggers programmatic completion at entry so the
// dependent ce kernel may begin its independent prologue (scores staging +
// exp) while IoU still runs; ce gridsyncs before touching g_kb/g_key.
// ---------------------------------------------------------------------------
__global__ __launch_bounds__(256) void iou_kernel(
    const float* __restrict__ boxes,    // [B,K,4] xyxy
    const float* __restrict__ priors)   // [P,4] cxcywh
{
    cudaTriggerProgrammaticLaunchCompletion();

    __shared__ float4 sbox[KK];
    __shared__ float  sarea[KK];
    __shared__ unsigned long long skey[KK][8];

    const int b    = blockIdx.x;
    const int tid  = threadIdx.x;
    const int lane = tid & 31;
    const int warp = tid >> 5;

    if (tid < KK) {
        float4 bx = reinterpret_cast<const float4*>(boxes)[b * KK + tid];
        sbox[tid]  = bx;
        sarea[tid] = (bx.z - bx.x) * (bx.w - bx.y);
    }
    __syncthreads();

    const int p = blockIdx.y * 256 + tid;
    const bool valid = (p < PP);

    unsigned int ib[KK];
    if (valid) {
        float4 pc = reinterpret_cast<const float4*>(priors)[p];
        float px0 = pc.x - pc.z * 0.5f;
        float py0 = pc.y - pc.w * 0.5f;
        float px1 = pc.x + pc.z * 0.5f;
        float py1 = pc.y + pc.w * 0.5f;
        float parea = (px1 - px0) * (py1 - py0);

        float vbest = -1e30f;
        int   kbest = 0;
#pragma unroll
        for (int k = 0; k < KK; k++) {
            float4 bx = sbox[k];
            float ltx = fmaxf(bx.x, px0);
            float lty = fmaxf(bx.y, py0);
            float rbx = fminf(bx.z, px1);
            float rby = fminf(bx.w, py1);
            float w = fmaxf(rbx - ltx, 0.0f);
            float h = fmaxf(rby - lty, 0.0f);
            float inter = w * h;
            float iou = exact_div(inter, sarea[k] + parea - inter); // == rn(a/b)
            ib[k] = __float_as_uint(iou);                     // iou >= 0
            if (iou > vbest) { vbest = iou; kbest = k; }      // first max over k
        }
        g_kb[b * PP + p] = (unsigned char)(kbest | ((vbest < THRESH) ? 0 : 16));
    } else {
#pragma unroll
        for (int k = 0; k < KK; k++) ib[k] = 0u;
    }

    const int pbase = blockIdx.y * 256 + warp * 32;   // p at lane 0 of this warp
#pragma unroll
    for (int k = 0; k < KK; k++) {
        unsigned int m = __reduce_max_sync(0xffffffffu, ib[k]);
        unsigned int ball = __ballot_sync(0xffffffffu, ib[k] == m);
        int src = __ffs(ball) - 1;                    // lowest lane = lowest p
        if (lane == 0)
            skey[k][warp] = ((unsigned long long)m << 32) |
                            (unsigned int)(~(unsigned int)(pbase + src));
    }
    __syncthreads();
    if (tid < KK) {
        unsigned long long best = skey[tid][0];
#pragma unroll
        for (int w = 1; w < 8; w++) {
            unsigned long long o = skey[tid][w];
            if (o > best) best = o;
        }
        atomicMax(&g_key[b * KK + tid], best);
    }
}

// ---------------------------------------------------------------------------
// Kernel 2: fused assign + CE + histogram build. One block per 64 rows,
// 256 threads. Launched with programmatic stream serialization: stages
// scores and runs the exp phase BEFORE cudaGridDependencySynchronize(),
// overlapping IoU; only then reads g_key/g_kb.
// ---------------------------------------------------------------------------
__global__ __launch_bounds__(256) void ce_kernel(
    const float* __restrict__ locs,     // [B,P,4]
    const float* __restrict__ scores,   // [B*P, C]
    const float* __restrict__ boxes,    // [B,K,4] xyxy
    const int*   __restrict__ labels,   // [B,K]
    const float* __restrict__ priors)   // [P,4] cxcywh
{
    cudaTriggerProgrammaticLaunchCompletion();   // releases select's launch

    __shared__ float sx[CE_ROWS * CC];   // 20736 B
    __shared__ float sp[256];            // exp partials
    __shared__ float sbx[2][KK * 4];
    __shared__ int   slab[2][KK];
    __shared__ int   spfo[2][KK];
    __shared__ int    snpos[2];
    __shared__ double sposce[2];
    __shared__ double sbox[2];

    const int tid  = threadIdx.x;
    const size_t row0 = (size_t)blockIdx.x * CE_ROWS;
    const int b0 = (int)(row0 / PP);
    const int b1 = (int)((row0 + CE_ROWS - 1) / PP);

    if (tid < 2) { snpos[tid] = 0; sposce[tid] = 0.0; sbox[tid] = 0.0; }

    // ---- independent prologue: stage scores + exp phase (overlaps IoU) ----
    const float4* src = reinterpret_cast<const float4*>(scores + row0 * CC);
    float4* dst = reinterpret_cast<float4*>(sx);
#pragma unroll
    for (int i = 0; i < 6; i++) {        // 6*256 = 1536 >= 1296
        int idx = tid + i * 256;
        if (idx < (CE_ROWS * CC) / 4) dst[idx] = src[idx];
    }
    __syncthreads();

    // exp phase: 4 threads per row; quarter q covers cols [q*20, q*20+20)
    // (+ col 80 for q==3). Row stride 81 odd -> conflict-free.
    {
        const int r = tid & 63;
        const int q = tid >> 6;
        const float* s = sx + r * CC;
        const int c0 = q * 20;
        float a0 = 0.f, a1 = 0.f, a2 = 0.f, a3 = 0.f;
#pragma unroll
        for (int i = 0; i < 5; i++) {
            int c = c0 + i * 4;
            a0 += __expf(s[c + 0]);
            a1 += __expf(s[c + 1]);
            a2 += __expf(s[c + 2]);
            a3 += __expf(s[c + 3]);
        }
        if (q == 3) a0 += __expf(s[80]);
        sp[tid] = (a0 + a1) + (a2 + a3);
    }

    // ---- wait for IoU results, then load matching state ----
    cudaGridDependencySynchronize();

#pragma unroll
    for (int j = 0; j < 2; j++) {
        int bb = b0 + j;
        if (bb <= b1) {
            if (tid < KK * 4) sbx[j][tid] = boxes[bb * KK * 4 + tid];
            if (tid < KK) {
                slab[j][tid] = labels[bb * KK + tid];
                spfo[j][tid] = (int)(~(unsigned int)(g_key[bb * KK + tid] & 0xffffffffu));
            }
        }
    }
    __syncthreads();                     // covers sp and spfo/slab/sbx

    if (tid < CE_ROWS) {
        const int row = (int)row0 + tid;
        int b = b0, p = row - b0 * PP;
        if (p >= PP) { b++; p -= PP; }
        const int j = b - b0;

        // force-assign label
        unsigned char kb = g_kb[row];
        int k   = kb & 15;
        int pos = (kb >> 4) & 1;
#pragma unroll
        for (int kk = 0; kk < KK; kk++)
            if (p == spfo[j][kk]) { k = kk; pos = 1; }   // ascending k, last wins
        const int lbl = pos ? slab[j][k] : 0;

        float lse = __logf((sp[tid] + sp[tid + 64]) +
                           (sp[tid + 128] + sp[tid + 192]));
        float ce = lse - sx[tid * CC + lbl];

        float v;
        if (lbl != 0) {
            v = 0.0f;
            g_ce_neg[row] = 0.0f;
            // encode + L1 for this positive prior
            float4 pc = reinterpret_cast<const float4*>(priors)[p];
            float bx0 = sbx[j][k * 4 + 0], by0 = sbx[j][k * 4 + 1];
            float bx1 = sbx[j][k * 4 + 2], by1 = sbx[j][k * 4 + 3];
            float t0 = ((bx0 + bx1) * 0.5f - pc.x) / (pc.z / 10.0f);
            float t1 = ((by0 + by1) * 0.5f - pc.y) / (pc.w / 10.0f);
            float t2 = logf((bx1 - bx0) / pc.z) * 5.0f;
            float t3 = logf((by1 - by0) / pc.w) * 5.0f;
            float4 pl = reinterpret_cast<const float4*>(locs)[row];
            float l1 = fabsf(pl.x - t0) + fabsf(pl.y - t1) +
                       fabsf(pl.z - t2) + fabsf(pl.w - t3);
            atomicAdd(&sposce[j], (double)ce);
            atomicAdd(&sbox[j],   (double)l1);
            atomicAdd(&snpos[j],  1);
        } else {
            v = fmaxf(ce, 0.0f);        // clamp: keeps uint order exact in select
            g_ce_neg[row] = v;
        }

        // selection histogram (positives contribute v=0 -> bin 0, count only)
        int bin = (lbl != 0) ? 0 : min((int)(v * 64.0f), NBINS - 1);
        atomicAdd(&g_hist[b * NBINS + bin], 1);
        if (v > 0.0f) atomicAdd(&g_fsum[b * NBINS + bin], v);
    }

    __syncthreads();
    if (tid < 2) {
        int bb = b0 + tid;
        if (bb <= b1 && snpos[tid] > 0) {
            atomicAdd(&g_npos[bb], snpos[tid]);
            atomicAdd(&g_npos_total, snpos[tid]);
            atomicAdd(&g_pos_ce, sposce[tid]);
            atomicAdd(&g_box,    sbox[tid]);
        }
    }
}

// ---------------------------------------------------------------------------
// Block-wide descending-cumulative bin selection over hist[nb] (nb=2048/1024).
// ---------------------------------------------------------------------------
__device__ __forceinline__ void suffix_select(
    const int* hist, int nb, int rem,
    int* wtot, int* hsum, int* s_bin, int* s_rem,
    int tid, int lane, int warp)
{
    int c0 = 0, c1 = 0, sfx0 = 0, sfx1 = 0, bin0 = -1, bin1 = -1;
    if (nb == 2048) {
        bin0 = warp * 64 + lane;
        bin1 = bin0 + 32;
        c0 = hist[bin0];
        c1 = hist[bin1];
        int x1 = c1;
#pragma unroll
        for (int off = 1; off < 32; off <<= 1) {
            int o = __shfl_down_sync(0xffffffffu, x1, off);
            if (lane + off < 32) x1 += o;
        }
        int tot1 = __shfl_sync(0xffffffffu, x1, 0);
        int x0 = c0;
#pragma unroll
        for (int off = 1; off < 32; off <<= 1) {
            int o = __shfl_down_sync(0xffffffffu, x0, off);
            if (lane + off < 32) x0 += o;
        }
        sfx1 = x1;
        sfx0 = x0 + tot1;
        if (lane == 0) wtot[warp] = sfx0;
    } else {
        bin0 = warp * 32 + lane;
        c0 = hist[bin0];
        int x0 = c0;
#pragma unroll
        for (int off = 1; off < 32; off <<= 1) {
            int o = __shfl_down_sync(0xffffffffu, x0, off);
            if (lane + off < 32) x0 += o;
        }
        sfx0 = x0;
        if (lane == 0) wtot[warp] = sfx0;
    }
    __syncthreads();
    if (warp == 0) {
        int v = (lane < 31) ? wtot[lane + 1] : 0;
#pragma unroll
        for (int off = 1; off < 32; off <<= 1) {
            int o = __shfl_down_sync(0xffffffffu, v, off);
            if (lane + off < 32) v += o;
        }
        hsum[lane] = v;
    }
    __syncthreads();
    {
        int add = hsum[warp];
        int t0 = sfx0 + add;
        if (t0 >= rem && t0 - c0 < rem) { *s_bin = bin0; *s_rem = rem - (t0 - c0); }
        if (bin1 >= 0) {
            int t1 = sfx1 + add;
            if (t1 >= rem && t1 - c1 < rem) { *s_bin = bin1; *s_rem = rem - (t1 - c1); }
        }
    }
    __syncthreads();
}

// ---------------------------------------------------------------------------
// Kernel 3: exact top-M sum of ce_neg per batch using the prebuilt histogram.
// Launched with programmatic stream serialization; gridsync at entry.
// One sweep (threshold-bin compaction) + exact radix over the compact list.
// Last block finalizes + resets scalars.
// ---------------------------------------------------------------------------
__global__ __launch_bounds__(1024) void select_kernel(float* __restrict__ out)
{
    cudaGridDependencySynchronize();

    __shared__ float sl[PP];           // fsum staging, then compact members
    __shared__ int   hist[NBINS];
    __shared__ int   wtot[32];
    __shared__ int   hsum[32];
    __shared__ double swarp[32];
    __shared__ int   s_bin;
    __shared__ int   s_rem;
    __shared__ int   s_M;
    __shared__ int   s_n;

    const int b    = blockIdx.x;
    const int tid  = threadIdx.x;
    const int lane = tid & 31;
    const int warp = tid >> 5;
    const float* __restrict__ src = g_ce_neg + b * PP;

    // load histogram + fsum (into sl[0..NBINS)) and reset globals for replay
    for (int i = tid; i < NBINS; i += 1024) {
        hist[i] = g_hist[b * NBINS + i];  g_hist[b * NBINS + i] = 0;
        sl[i]   = g_fsum[b * NBINS + i];  g_fsum[b * NBINS + i] = 0.0f;
    }
    if (tid == 0) {
        int M = 3 * g_npos[b];
        if (M > PP) M = PP;
        s_M = M;
        s_n = 0;
        g_npos[b] = 0;                         // reset for next replay
    }
    if (tid < KK) g_key[b * KK + tid] = 0ull;  // reset for next replay
    __syncthreads();
    const int M = s_M;

    if (M > 0) {
        suffix_select(hist, NBINS, M, wtot, hsum, &s_bin, &s_rem, tid, lane, warp);
        const int cbin = s_bin;
        int rem = s_rem;

        // sum of all fully-selected bins (above threshold bin)
        double acc = 0.0;
        for (int i = tid; i < NBINS; i += 1024)
            if (i > cbin) acc += (double)sl[i];
        __syncthreads();   // done reading sl as fsum

        // one sweep: compact threshold-bin members into sl
        for (int i = tid; i < PP; i += 1024) {
            float vv = src[i];
            int bin = min((int)(vv * 64.0f), NBINS - 1);
            if (bin == cbin) sl[atomicAdd(&s_n, 1)] = vv;
        }
        __syncthreads();
        const int n = s_n;

        // exact radix over the compact list (3 passes 11/11/10)
        unsigned int pfx = 0;
#pragma unroll
        for (int pass = 0; pass < 3; pass++) {
            const int nb = (pass == 2) ? 1024 : 2048;
            for (int i = tid; i < NBINS; i += 1024) hist[i] = 0;
            __syncthreads();

            for (int i = tid; i < ((n + 1023) & ~1023); i += 1024) {
                unsigned int key = 0xffffffffu;
                unsigned int bn = 0;
                if (i < n) {
                    unsigned int u = __float_as_uint(sl[i]);
                    bool ok;
                    if (pass == 0)      { ok = true;                bn = u >> 21; }
                    else if (pass == 1) { ok = ((u >> 21) == pfx);  bn = (u >> 10) & 2047u; }
                    else                { ok = ((u >> 10) == pfx);  bn = u & 1023u; }
                    if (ok) key = bn;
                }
                unsigned int peers = __match_any_sync(0xffffffffu, key);
                if (key != 0xffffffffu) {
                    int leader = __ffs(peers) - 1;
                    if (lane == leader) atomicAdd(&hist[bn], __popc(peers));
                }
            }
            __syncthreads();

            suffix_select(hist, nb, rem, wtot, hsum, &s_bin, &s_rem, tid, lane, warp);
            pfx = (pass == 2) ? ((pfx << 10) | (unsigned)s_bin)
                              : ((pfx << 11) | (unsigned)s_bin);
            rem = s_rem;
            __syncthreads();
        }

        const unsigned int Tu = pfx;
        const float T = __uint_as_float(Tu);

        for (int i = tid; i < n; i += 1024) {
            float vv = sl[i];
            if (__float_as_uint(vv) > Tu) acc += (double)vv;
        }

#pragma unroll
        for (int off = 16; off > 0; off >>= 1)
            acc += __shfl_xor_sync(0xffffffffu, acc, off);
        if (lane == 0) swarp[warp] = acc;
        __syncthreads();
        if (warp == 0) {
            double vv = swarp[lane];
#pragma unroll
            for (int off = 16; off > 0; off >>= 1)
                vv += __shfl_xor_sync(0xffffffffu, vv, off);
            if (lane == 0) atomicAdd(&g_hard, vv + (double)rem * (double)T);
        }
        __syncthreads();
    }

    if (tid == 0) {
        __threadfence();
        unsigned int old = atomicAdd(&g_done, 1u);
        if (old == BB - 1) {
            double np = (double)g_npos_total;
            out[0] = (float)((g_pos_ce + g_hard) / np + g_box / (np * 4.0));
            // reset scalars for next graph replay
            g_pos_ce = 0.0;
            g_hard   = 0.0;
            g_box    = 0.0;
            g_npos_total = 0;
            g_done   = 0u;
        }
    }
}

extern "C" void kernel_launch(void* const* d_in, const int* in_sizes, int n_in,
                              void* d_out, int out_size)
{
    const float* locs   = (const float*)d_in[0];  // [B,P,4]
    const float* scores = (const float*)d_in[1];  // [B,P,C]
    const float* boxes  = (const float*)d_in[2];  // [B,K,4]
    const int*   labels = (const int*)d_in[3];    // [B,K]
    const float* priors = (const float*)d_in[4];  // [P,4]
    float* out = (float*)d_out;

    iou_kernel<<<dim3(BB, SPLIT_A), 256>>>(boxes, priors);

    cudaLaunchAttribute attr[1];
    attr[0].id = cudaLaunchAttributeProgrammaticStreamSerialization;
    attr[0].val.programmaticStreamSerializationAllowed = 1;

    cudaLaunchConfig_t cfg = {};
    cfg.gridDim  = dim3(CE_BLOCKS);
    cfg.blockDim = dim3(256);
    cfg.dynamicSmemBytes = 0;
    cfg.stream = 0;
    cfg.attrs = attr;
    cfg.numAttrs = 1;
    cudaLaunchKernelEx(&cfg, ce_kernel, locs, scores, boxes, labels, priors);

    cudaLaunchConfig_t cfg2 = {};
    cfg2.gridDim  = dim3(BB);
    cfg2.blockDim = dim3(1024);
    cfg2.dynamicSmemBytes = 0;
    cfg2.stream = 0;
    cfg2.attrs = attr;
    cfg2.numAttrs = 1;
    cudaLaunchKernelEx(&cfg2, select_kernel, out);
}